// round 5
// baseline (speedup 1.0000x reference)
#include <cuda_runtime.h>

// out = noised + 0.1f * noise over 50,331,648 fp32 (12,582,912 float4).
// Pure HBM stream at the bandwidth floor (~6.9 TB/s achieved). Single
// launch: tail (n % 4, zero for this shape) folded into the main kernel
// so the captured graph has exactly one node.

__global__ void __launch_bounds__(256) gnoise_kernel(
    const float4* __restrict__ noised,
    const float4* __restrict__ noise,
    float4* __restrict__ out,
    int n4,   // n / 4
    int n)    // total elements
{
    int i = blockIdx.x * blockDim.x + threadIdx.x;
    if (i < n4) {
        float4 a = __ldcs(noised + i);
        float4 b = __ldcs(noise + i);
        float4 r;
        r.x = fmaf(0.1f, b.x, a.x);
        r.y = fmaf(0.1f, b.y, a.y);
        r.z = fmaf(0.1f, b.z, a.z);
        r.w = fmaf(0.1f, b.w, a.w);
        __stcs(out + i, r);
    } else if (i == n4) {
        // Scalar tail: elements [4*n4, n). Empty when n % 4 == 0.
        const float* ns = (const float*)noised;
        const float* nz = (const float*)noise;
        float* o = (float*)out;
        for (int j = 4 * n4; j < n; j++)
            o[j] = fmaf(0.1f, nz[j], ns[j]);
    }
}

extern "C" void kernel_launch(void* const* d_in, const int* in_sizes, int n_in,
                              void* d_out, int out_size)
{
    const float* noised = (const float*)d_in[0];
    const float* noise  = (const float*)d_in[1];
    float* out = (float*)d_out;
    int n = in_sizes[0];

    int n4 = n / 4;
    // Cover n4 vector slots plus one extra thread slot for the scalar tail.
    int work = n4 + ((n & 3) ? 1 : 0);
    if (work == 0) return;
    const int threads = 256;
    int blocks = (work + threads - 1) / threads;
    gnoise_kernel<<<blocks, threads>>>(
        (const float4*)noised, (const float4*)noise, (float4*)out, n4, n);
}